// round 6
// baseline (speedup 1.0000x reference)
#include <cuda_runtime.h>

#define NB 26
#define POSE_F 78        // 26*3 floats per pose
#define PPAD 79          // padded per-thread stride: gcd(79,32)=1 -> conflict-free
#define TPB 64
#define BATCH 131072

#define TAB_F (NB * 5 + NB * 3)   // 130 rr5 entries + 78 rel_loc = 208

// Staging global filled by the pre-kernel (rr5 then rl), then copied once
// into __constant__ via a stream-ordered D2D memcpy (graph-capturable node).
__device__ float g_tab[TAB_F];
__constant__ float c_tab[TAB_F];

#define C_RR5(i) c_tab[(i)]
#define C_RL(i)  c_tab[NB * 5 + (i)]

struct M3 { float a[9]; };
struct V3 { float v[3]; };

// approx sqrt: t * rsqrt(t), safe near 0 after clamping
__device__ __forceinline__ float fsqrt_approx(float t) {
    t = fmaxf(t, 1e-30f);
    return t * rsqrtf(t);
}

// Full bone step: abs_loc + rotation chain update.
// Ap/bp passed BY VALUE so Ao/bo may alias the caller's current state.
// bone is a compile-time literal at every call site -> LDC with immediate offset.
__device__ __forceinline__ void fullstep(int bone, M3 Ap, V3 bp, M3& Ao, V3& bo,
                                         float* __restrict__ P)
{
    const float lx = C_RL(bone * 3 + 0);
    const float ly = C_RL(bone * 3 + 1);
    const float lz = C_RL(bone * 3 + 2);

    // abs_loc[bone] = l . Ap + bp   (row-vector times matrix)
    float ax = lx * Ap.a[0] + ly * Ap.a[3] + lz * Ap.a[6] + bp.v[0];
    float ay = lx * Ap.a[1] + ly * Ap.a[4] + lz * Ap.a[7] + bp.v[1];
    float az = lx * Ap.a[2] + ly * Ap.a[5] + lz * Ap.a[8] + bp.v[2];

    // read this bone's euler angles, then overwrite the slot with abs_loc (in-place)
    float ez = P[bone * 3 + 0];
    float ey = P[bone * 3 + 1];
    float ex = P[bone * 3 + 2];
    P[bone * 3 + 0] = ax;
    P[bone * 3 + 1] = ay;
    P[bone * 3 + 2] = az;

    float sz, cz, sy, cy, sx, cx;
    __sincosf(ez, &sz, &cz);
    __sincosf(ey, &sy, &cy);
    __sincosf(ex, &sx, &cx);

    // Only 5 entries of M = R_ref (hadamard) R_chg are needed by matrix_to_euler:
    // m00 = cz*cy, m10 = sz*cy, m20 = -sy, m21 = cy*sx, m22 = cy*cx
    float M00 = C_RR5(bone * 5 + 0) * (cz * cy);
    float M10 = C_RR5(bone * 5 + 1) * (sz * cy);
    float M20 = C_RR5(bone * 5 + 2) * (-sy);
    float M21 = C_RR5(bone * 5 + 3) * (cy * sx);
    float M22 = C_RR5(bone * 5 + 4) * (cy * cx);

    // Trig-free euler->matrix rebuild:
    // z = atan2(M10, M00)  ->  cos = M00/h, sin = M10/h
    // y = asin(-M20)       ->  sin = -M20,  cos = sqrt(1 - sin^2) (>= 0)
    // x = atan2(M21, M22)  ->  cos = M22/h, sin = M21/h
    float i0 = rsqrtf(fmaxf(M00 * M00 + M10 * M10, 1e-30f));
    float CZ = M00 * i0, SZ = M10 * i0;
    float SY = -M20;
    float CY = fsqrt_approx(1.0f - SY * SY);
    float i2 = rsqrtf(fmaxf(M21 * M21 + M22 * M22, 1e-30f));
    float CX = M22 * i2, SX = M21 * i2;

    // Rebuilt rotation R (ZYX euler)
    float R00 = CZ * CY;
    float R01 = CZ * SY * SX - SZ * CX;
    float R02 = CZ * SY * CX + SZ * SX;
    float R10 = SZ * CY;
    float R11 = SZ * SY * SX + CZ * CX;
    float R12 = SZ * SY * CX - CZ * SX;
    float R20 = -SY;
    float R21 = CY * SX;
    float R22 = CY * CX;

    // A_new = Ap @ R
    M3 T;
    #pragma unroll
    for (int k = 0; k < 3; k++) {
        float a0 = Ap.a[3 * k + 0], a1 = Ap.a[3 * k + 1], a2 = Ap.a[3 * k + 2];
        T.a[3 * k + 0] = a0 * R00 + a1 * R10 + a2 * R20;
        T.a[3 * k + 1] = a0 * R01 + a1 * R11 + a2 * R21;
        T.a[3 * k + 2] = a0 * R02 + a1 * R12 + a2 * R22;
    }
    // b_new = (bp + l) . R
    float tx = bp.v[0] + lx, ty = bp.v[1] + ly, tz = bp.v[2] + lz;
    V3 tb;
    tb.v[0] = tx * R00 + ty * R10 + tz * R20;
    tb.v[1] = tx * R01 + ty * R11 + tz * R21;
    tb.v[2] = tx * R02 + ty * R12 + tz * R22;

    Ao = T;
    bo = tb;
}

// Leaf bone: only abs_loc needed (its rotation is never consumed).
__device__ __forceinline__ void leafstep(int bone, const M3& Ap, const V3& bp,
                                         float* __restrict__ P)
{
    const float lx = C_RL(bone * 3 + 0);
    const float ly = C_RL(bone * 3 + 1);
    const float lz = C_RL(bone * 3 + 2);
    P[bone * 3 + 0] = lx * Ap.a[0] + ly * Ap.a[3] + lz * Ap.a[6] + bp.v[0];
    P[bone * 3 + 1] = lx * Ap.a[1] + ly * Ap.a[4] + lz * Ap.a[7] + bp.v[1];
    P[bone * 3 + 2] = lx * Ap.a[2] + ly * Ap.a[5] + lz * Ap.a[8] + bp.v[2];
}

// Tiny pre-kernel: accurate trig once for the 26 reference rotations,
// plus copy rel_loc, all into one staging table.
__global__ void ref_table_kernel(const float* __restrict__ rel_rot_ref,
                                 const float* __restrict__ rel_loc)
{
    int i = threadIdx.x;
    if (i < NB) {
        float ez = rel_rot_ref[i * 3 + 0];
        float ey = rel_rot_ref[i * 3 + 1];
        float ex = rel_rot_ref[i * 3 + 2];
        float sz, cz, sy, cy, sx, cx;
        sincosf(ez, &sz, &cz);
        sincosf(ey, &sy, &cy);
        sincosf(ex, &sx, &cx);
        g_tab[i * 5 + 0] = cz * cy;   // m00
        g_tab[i * 5 + 1] = sz * cy;   // m10
        g_tab[i * 5 + 2] = -sy;       // m20
        g_tab[i * 5 + 3] = cy * sx;   // m21
        g_tab[i * 5 + 4] = cy * cx;   // m22
    }
    for (int j = i; j < NB * 3; j += blockDim.x)
        g_tab[NB * 5 + j] = rel_loc[j];
}

__global__ void __launch_bounds__(TPB, 11)
fk_kernel(const float* __restrict__ x,
          float* __restrict__ out)
{
    // Padded layout: pose p element k lives at pose[p*PPAD + k].
    __shared__ float pose[TPB * PPAD];

    const int tid = threadIdx.x;

    // Coalesced float4 staging with 78 -> 79 stride remap.
    // NV4 = 1248 float4 loads; each scatters 4 floats into padded shared.
    const int NV4 = TPB * POSE_F / 4;                 // 1248
    const int NIT = (NV4 + TPB - 1) / TPB;            // 20
    const float4* gin = reinterpret_cast<const float4*>(x) + (size_t)blockIdx.x * NV4;
    #pragma unroll
    for (int i = 0; i < NIT; i++) {
        int idx = tid + i * TPB;
        if (idx < NV4) {
            float4 v = gin[idx];
            int e = idx * 4;                 // flat element index within block
            int p = e / POSE_F;              // pose (constexpr divisor -> mulhi)
            int k = e - p * POSE_F;
            // 4 consecutive elements may cross a pose boundary (78 not mult of 4)
            float vv[4] = {v.x, v.y, v.z, v.w};
            #pragma unroll
            for (int j = 0; j < 4; j++) {
                int pp = p, kk = k + j;
                if (kk >= POSE_F) { pp++; kk -= POSE_F; }
                pose[pp * PPAD + kk] = vv[j];
            }
        }
    }
    __syncthreads();

    float* P = pose + tid * PPAD;

    M3 A, Asv;
    V3 b, bsv;

    // bone 0 (root): Ap = I, bp = 0 (constant-folded)
    {
        M3 I; V3 z;
        I.a[0] = 1.f; I.a[1] = 0.f; I.a[2] = 0.f;
        I.a[3] = 0.f; I.a[4] = 1.f; I.a[5] = 0.f;
        I.a[6] = 0.f; I.a[7] = 0.f; I.a[8] = 1.f;
        z.v[0] = 0.f; z.v[1] = 0.f; z.v[2] = 0.f;
        fullstep(0, I, z, A, b, P);
    }
    fullstep(1, A, b, Asv, bsv, P);   // Asv = A1

    // limbs rooted at bone 1 (done now so A1 needn't stay live later)
    fullstep(15, Asv, bsv, A, b, P);
    fullstep(16, A, b, A, b, P);
    fullstep(17, A, b, A, b, P);
    leafstep(18, A, b, P);
    fullstep(19, Asv, bsv, A, b, P);
    fullstep(20, A, b, A, b, P);
    fullstep(21, A, b, A, b, P);
    leafstep(22, A, b, P);

    // spine 2,3,4 (continue from A1)
    fullstep(2, Asv, bsv, A, b, P);
    fullstep(3, A, b, A, b, P);
    fullstep(4, A, b, Asv, bsv, P);   // Asv = A4

    // limbs rooted at bone 4
    fullstep(7, Asv, bsv, A, b, P);
    fullstep(8, A, b, A, b, P);
    fullstep(9, A, b, A, b, P);
    leafstep(10, A, b, P);
    fullstep(11, Asv, bsv, A, b, P);
    fullstep(12, A, b, A, b, P);
    fullstep(13, A, b, A, b, P);
    leafstep(14, A, b, P);

    // spine 5,6 + head leaves
    fullstep(5, Asv, bsv, A, b, P);
    fullstep(6, A, b, A, b, P);
    leafstep(23, A, b, P);
    leafstep(24, A, b, P);
    leafstep(25, A, b, P);

    __syncthreads();

    // Coalesced float4 write-back (gather from padded shared)
    float4* gout = reinterpret_cast<float4*>(out) + (size_t)blockIdx.x * NV4;
    #pragma unroll
    for (int i = 0; i < NIT; i++) {
        int idx = tid + i * TPB;
        if (idx < NV4) {
            int e = idx * 4;
            int p = e / POSE_F;
            int k = e - p * POSE_F;
            float vv[4];
            #pragma unroll
            for (int j = 0; j < 4; j++) {
                int pp = p, kk = k + j;
                if (kk >= POSE_F) { pp++; kk -= POSE_F; }
                vv[j] = pose[pp * PPAD + kk];
            }
            gout[idx] = make_float4(vv[0], vv[1], vv[2], vv[3]);
        }
    }
}

extern "C" void kernel_launch(void* const* d_in, const int* in_sizes, int n_in,
                              void* d_out, int out_size)
{
    const float* x           = (const float*)d_in[0];  // (131072, 26, 3)
    const float* rel_loc     = (const float*)d_in[1];  // (26, 3)
    const float* rel_rot_ref = (const float*)d_in[2];  // (26, 3)
    float* out               = (float*)d_out;          // (131072, 26, 3)

    const int batch = in_sizes[0] / POSE_F;            // 131072

    // 1) accurate trig for the 26 reference rotations + rel_loc -> g_tab
    ref_table_kernel<<<1, 128>>>(rel_rot_ref, rel_loc);

    // 2) one stream-ordered D2D copy into __constant__ (graph-capturable node)
    void* g_tab_ptr = nullptr;
    cudaGetSymbolAddress(&g_tab_ptr, g_tab);
    cudaMemcpyToSymbolAsync(c_tab, g_tab_ptr, sizeof(float) * TAB_F, 0,
                            cudaMemcpyDeviceToDevice, 0);

    // 3) main kernel
    fk_kernel<<<batch / TPB, TPB>>>(x, out);
}

// round 7
// speedup vs baseline: 1.8595x; 1.8595x over previous
#include <cuda_runtime.h>

#define NB 26
#define POSE_F 78        // 26*3 floats per pose
#define TPB 64
#define BATCH 131072

#define TAB_F (NB * 5 + NB * 3)   // 130 rr5 entries + 78 rel_loc = 208

// Staging global filled by the pre-kernel (rr5 then rl), then copied once
// into __constant__ via a stream-ordered D2D memcpy (graph-capturable node).
__device__ float g_tab[TAB_F];
__constant__ float c_tab[TAB_F];

#define C_RR5(i) c_tab[(i)]
#define C_RL(i)  c_tab[NB * 5 + (i)]

struct M3 { float a[9]; };
struct V3 { float v[3]; };

// approx sqrt: t * rsqrt(t), safe near 0 after clamping
__device__ __forceinline__ float fsqrt_approx(float t) {
    t = fmaxf(t, 1e-30f);
    return t * rsqrtf(t);
}

// Full bone step: abs_loc + rotation chain update.
// Ap/bp passed BY VALUE so Ao/bo may alias the caller's current state.
// bone is a compile-time literal at every call site -> LDC with immediate offset.
__device__ __forceinline__ void fullstep(int bone, M3 Ap, V3 bp, M3& Ao, V3& bo,
                                         float* __restrict__ P)
{
    const float lx = C_RL(bone * 3 + 0);
    const float ly = C_RL(bone * 3 + 1);
    const float lz = C_RL(bone * 3 + 2);

    // abs_loc[bone] = l . Ap + bp   (row-vector times matrix)
    float ax = lx * Ap.a[0] + ly * Ap.a[3] + lz * Ap.a[6] + bp.v[0];
    float ay = lx * Ap.a[1] + ly * Ap.a[4] + lz * Ap.a[7] + bp.v[1];
    float az = lx * Ap.a[2] + ly * Ap.a[5] + lz * Ap.a[8] + bp.v[2];

    // read this bone's euler angles, then overwrite the slot with abs_loc (in-place)
    float ez = P[bone * 3 + 0];
    float ey = P[bone * 3 + 1];
    float ex = P[bone * 3 + 2];
    P[bone * 3 + 0] = ax;
    P[bone * 3 + 1] = ay;
    P[bone * 3 + 2] = az;

    float sz, cz, sy, cy, sx, cx;
    __sincosf(ez, &sz, &cz);
    __sincosf(ey, &sy, &cy);
    __sincosf(ex, &sx, &cx);

    // Only 5 entries of M = R_ref (hadamard) R_chg are needed by matrix_to_euler:
    // m00 = cz*cy, m10 = sz*cy, m20 = -sy, m21 = cy*sx, m22 = cy*cx
    float M00 = C_RR5(bone * 5 + 0) * (cz * cy);
    float M10 = C_RR5(bone * 5 + 1) * (sz * cy);
    float M20 = C_RR5(bone * 5 + 2) * (-sy);
    float M21 = C_RR5(bone * 5 + 3) * (cy * sx);
    float M22 = C_RR5(bone * 5 + 4) * (cy * cx);

    // Trig-free euler->matrix rebuild:
    // z = atan2(M10, M00)  ->  cos = M00/h, sin = M10/h
    // y = asin(-M20)       ->  sin = -M20,  cos = sqrt(1 - sin^2) (>= 0)
    // x = atan2(M21, M22)  ->  cos = M22/h, sin = M21/h
    float i0 = rsqrtf(fmaxf(M00 * M00 + M10 * M10, 1e-30f));
    float CZ = M00 * i0, SZ = M10 * i0;
    float SY = -M20;
    float CY = fsqrt_approx(1.0f - SY * SY);
    float i2 = rsqrtf(fmaxf(M21 * M21 + M22 * M22, 1e-30f));
    float CX = M22 * i2, SX = M21 * i2;

    // Rebuilt rotation R (ZYX euler)
    float R00 = CZ * CY;
    float R01 = CZ * SY * SX - SZ * CX;
    float R02 = CZ * SY * CX + SZ * SX;
    float R10 = SZ * CY;
    float R11 = SZ * SY * SX + CZ * CX;
    float R12 = SZ * SY * CX - CZ * SX;
    float R20 = -SY;
    float R21 = CY * SX;
    float R22 = CY * CX;

    // A_new = Ap @ R
    M3 T;
    #pragma unroll
    for (int k = 0; k < 3; k++) {
        float a0 = Ap.a[3 * k + 0], a1 = Ap.a[3 * k + 1], a2 = Ap.a[3 * k + 2];
        T.a[3 * k + 0] = a0 * R00 + a1 * R10 + a2 * R20;
        T.a[3 * k + 1] = a0 * R01 + a1 * R11 + a2 * R21;
        T.a[3 * k + 2] = a0 * R02 + a1 * R12 + a2 * R22;
    }
    // b_new = (bp + l) . R
    float tx = bp.v[0] + lx, ty = bp.v[1] + ly, tz = bp.v[2] + lz;
    V3 tb;
    tb.v[0] = tx * R00 + ty * R10 + tz * R20;
    tb.v[1] = tx * R01 + ty * R11 + tz * R21;
    tb.v[2] = tx * R02 + ty * R12 + tz * R22;

    Ao = T;
    bo = tb;
}

// Leaf bone: only abs_loc needed (its rotation is never consumed).
__device__ __forceinline__ void leafstep(int bone, const M3& Ap, const V3& bp,
                                         float* __restrict__ P)
{
    const float lx = C_RL(bone * 3 + 0);
    const float ly = C_RL(bone * 3 + 1);
    const float lz = C_RL(bone * 3 + 2);
    P[bone * 3 + 0] = lx * Ap.a[0] + ly * Ap.a[3] + lz * Ap.a[6] + bp.v[0];
    P[bone * 3 + 1] = lx * Ap.a[1] + ly * Ap.a[4] + lz * Ap.a[7] + bp.v[1];
    P[bone * 3 + 2] = lx * Ap.a[2] + ly * Ap.a[5] + lz * Ap.a[8] + bp.v[2];
}

// Tiny pre-kernel: accurate trig once for the 26 reference rotations,
// plus copy rel_loc, all into one staging table.
__global__ void ref_table_kernel(const float* __restrict__ rel_rot_ref,
                                 const float* __restrict__ rel_loc)
{
    int i = threadIdx.x;
    if (i < NB) {
        float ez = rel_rot_ref[i * 3 + 0];
        float ey = rel_rot_ref[i * 3 + 1];
        float ex = rel_rot_ref[i * 3 + 2];
        float sz, cz, sy, cy, sx, cx;
        sincosf(ez, &sz, &cz);
        sincosf(ey, &sy, &cy);
        sincosf(ex, &sx, &cx);
        g_tab[i * 5 + 0] = cz * cy;   // m00
        g_tab[i * 5 + 1] = sz * cy;   // m10
        g_tab[i * 5 + 2] = -sy;       // m20
        g_tab[i * 5 + 3] = cy * sx;   // m21
        g_tab[i * 5 + 4] = cy * cx;   // m22
    }
    for (int j = i; j < NB * 3; j += blockDim.x)
        g_tab[NB * 5 + j] = rel_loc[j];
}

__global__ void __launch_bounds__(TPB, 11)
fk_kernel(const float* __restrict__ x,
          float* __restrict__ out)
{
    __shared__ float pose[TPB * POSE_F];   // linear layout (round-5 proven best)

    const int tid = threadIdx.x;

    // Coalesced float4 staging, STS.128, predicated tail.
    const int NV4 = TPB * POSE_F / 4;                 // 1248
    const int NIT = (NV4 + TPB - 1) / TPB;            // 20
    const float4* gin = reinterpret_cast<const float4*>(x) + (size_t)blockIdx.x * NV4;
    float4* sp4 = reinterpret_cast<float4*>(pose);
    #pragma unroll
    for (int i = 0; i < NIT; i++) {
        int idx = tid + i * TPB;
        if (idx < NV4) sp4[idx] = gin[idx];
    }
    __syncthreads();

    float* P = pose + tid * POSE_F;

    M3 Aa, Ab, As;
    V3 ba, bb, bs;

    // root + bone 1 (serial prefix)
    {
        M3 I; V3 z;
        I.a[0] = 1.f; I.a[1] = 0.f; I.a[2] = 0.f;
        I.a[3] = 0.f; I.a[4] = 1.f; I.a[5] = 0.f;
        I.a[6] = 0.f; I.a[7] = 0.f; I.a[8] = 1.f;
        z.v[0] = 0.f; z.v[1] = 0.f; z.v[2] = 0.f;
        fullstep(0, I, z, As, bs, P);
    }
    fullstep(1, As, bs, As, bs, P);   // As = A1 state

    // Three independent chains off bone 1, interleaved for ILP:
    //   chain a: 15,16,17,(18)   chain b: 19,20,21,(22)   spine: 2,3,4
    fullstep(15, As, bs, Aa, ba, P);
    fullstep(19, As, bs, Ab, bb, P);
    fullstep(2,  As, bs, As, bs, P);
    fullstep(16, Aa, ba, Aa, ba, P);
    fullstep(20, Ab, bb, Ab, bb, P);
    fullstep(3,  As, bs, As, bs, P);
    fullstep(17, Aa, ba, Aa, ba, P);
    fullstep(21, Ab, bb, Ab, bb, P);
    fullstep(4,  As, bs, As, bs, P);
    leafstep(18, Aa, ba, P);
    leafstep(22, Ab, bb, P);

    // Three independent chains off bone 4, interleaved:
    //   chain a: 7,8,9,(10)   chain b: 11,12,13,(14)   spine: 5,6 + head leaves
    fullstep(7,  As, bs, Aa, ba, P);
    fullstep(11, As, bs, Ab, bb, P);
    fullstep(5,  As, bs, As, bs, P);
    fullstep(8,  Aa, ba, Aa, ba, P);
    fullstep(12, Ab, bb, Ab, bb, P);
    fullstep(6,  As, bs, As, bs, P);
    fullstep(9,  Aa, ba, Aa, ba, P);
    fullstep(13, Ab, bb, Ab, bb, P);
    leafstep(23, As, bs, P);
    leafstep(10, Aa, ba, P);
    leafstep(14, Ab, bb, P);
    leafstep(24, As, bs, P);
    leafstep(25, As, bs, P);

    __syncthreads();

    // Coalesced float4 write-back
    float4* gout = reinterpret_cast<float4*>(out) + (size_t)blockIdx.x * NV4;
    #pragma unroll
    for (int i = 0; i < NIT; i++) {
        int idx = tid + i * TPB;
        if (idx < NV4) gout[idx] = sp4[idx];
    }
}

extern "C" void kernel_launch(void* const* d_in, const int* in_sizes, int n_in,
                              void* d_out, int out_size)
{
    const float* x           = (const float*)d_in[0];  // (131072, 26, 3)
    const float* rel_loc     = (const float*)d_in[1];  // (26, 3)
    const float* rel_rot_ref = (const float*)d_in[2];  // (26, 3)
    float* out               = (float*)d_out;          // (131072, 26, 3)

    const int batch = in_sizes[0] / POSE_F;            // 131072

    // 1) accurate trig for the 26 reference rotations + rel_loc -> g_tab
    ref_table_kernel<<<1, 128>>>(rel_rot_ref, rel_loc);

    // 2) one stream-ordered D2D copy into __constant__ (graph-capturable node)
    void* g_tab_ptr = nullptr;
    cudaGetSymbolAddress(&g_tab_ptr, g_tab);
    cudaMemcpyToSymbolAsync(c_tab, g_tab_ptr, sizeof(float) * TAB_F, 0,
                            cudaMemcpyDeviceToDevice, 0);

    // 3) main kernel
    fk_kernel<<<batch / TPB, TPB>>>(x, out);
}